// round 12
// baseline (speedup 1.0000x reference)
#include <cuda_runtime.h>

// HoG layer, fused. Phase 1 = R3 scattered gather (2 cells/thread, 24 LDGs
// in flight). Phase 2 = WARP-PER-BLOCK: lane c owns component c, ssq by
// shfl butterfly, stores are one contiguous 144B run per block (2 store
// wavefronts vs 9) with no SMEM staging and no extra barrier.
//   input  x: (1, 3, 4096, 4096) f32 ; output feat: (511, 511, 36) f32

#define IMG   4096
#define CELLS 512
#define OUTD  511
#define TC    16          // cells per tile side
#define HW    (TC + 1)    // 17: tile + halo
#define NCELL (HW * HW)   // 289
#define NT    256

__global__ __launch_bounds__(NT)
void hog_fused_kernel(const float* __restrict__ x, float* __restrict__ out)
{
    __shared__ __align__(16) float hist[NCELL * 9];   // 10404 B

    const int cx0 = blockIdx.x * TC;
    const int cy0 = blockIdx.y * TC;
    const int tid = threadIdx.x;
    const long chs = (long)IMG * IMG;

    // Zero hist slots this thread owns (same ownership as fill, no barrier).
    for (int c = tid; c < NCELL; c += NT) {
        #pragma unroll
        for (int b = 0; b < 9; b++) hist[c * 9 + b] = 0.0f;
    }

    // ---- Phase 1: two cells per thread, all 24 loads issued up front ----
    float v[2][12];
    bool  valid[2];
    const float* base[2];
    bool  hd[2], hr[2];

    #pragma unroll
    for (int it = 0; it < 2; it++) {
        const int c = tid + it * NT;
        const int lcy = c / HW;
        const int lcx = c - lcy * HW;
        const int cy = cy0 + lcy;
        const int cx = cx0 + lcx;
        valid[it] = (c < NCELL) && (cy < CELLS) && (cx < CELLS);
        const int py = cy * 8 + 7;
        const int px = cx * 8 + 7;
        base[it] = x + (long)py * IMG + px;
        hd[it] = (py + 1 < IMG);
        hr[it] = (px + 1 < IMG);
    }

    #pragma unroll
    for (int it = 0; it < 2; it++) {
        const float* p = base[it];
        const bool va = valid[it];
        const bool vd = va && hd[it];
        const bool vr = va && hr[it];
        #pragma unroll
        for (int ch = 0; ch < 3; ch++) {
            const float* pc = p + ch * chs;
            v[it][ch * 4 + 0] = va ? pc[-IMG] : 0.0f;
            v[it][ch * 4 + 1] = va ? pc[-1]   : 0.0f;
            v[it][ch * 4 + 2] = vd ? pc[IMG]  : 0.0f;
            v[it][ch * 4 + 3] = vr ? pc[1]    : 0.0f;
        }
    }

    #pragma unroll
    for (int it = 0; it < 2; it++) {
        if (!valid[it]) continue;
        const float su = v[it][0] + v[it][4] + v[it][8];
        const float sl = v[it][1] + v[it][5] + v[it][9];
        const float sd = v[it][2] + v[it][6] + v[it][10];
        const float sr = v[it][3] + v[it][7] + v[it][11];

        const float gv = sd - su;
        const float gh = sr - sl;
        const float mag = sqrtf(gv * gv + gh * gh + 1e-6f);
        const float ang = fabsf(atanf(gh / (gv + 1e-9f)))
                          * (180.0f / 3.14159265358979323846f);

        const float t  = ang * 0.05f;                 // ang / 20
        const int   ji = (int)floorf(t - 0.5f);       // in [-1, 4]
        const float vj  = mag * ((float)ji + 1.5f - t);
        const float vj1 = mag - vj;

        const int i0 = (ji < 0) ? 8 : ji;   // mod(ji, 9)
        const int i1 = ji + 1;              // never == i0
        float* hrow = &hist[(tid + it * NT) * 9];
        hrow[i0] = vj;
        hrow[i1] = vj1;
    }
    __syncthreads();

    // ---- Phase 2: warp-per-block, contiguous stores ----
    const int warp = tid >> 5;
    const int lane = tid & 31;

    // Component->hist-offset for this lane (uniform across blocks).
    // comp i: segment s = i/9 in {h00,h01,h10,h11}, bin b = i%9
    const int s1 = lane / 9;                 // 0..3 (lane 0..31 -> comps 0..31)
    const int b1 = lane - s1 * 9;
    const int off1 = ((s1 & 1) ? 9 : 0) + ((s1 & 2) ? HW * 9 : 0) + b1;
    const int off2 = HW * 9 + 9 + (lane + 5) - 9;     // comp 32+lane: s=3, b=lane+5... 
    // comp c2 = 32 + lane (lanes 0..3): s=3 always (32..35 -> b=5..8)
    const int off2b = HW * 9 + 9 + (5 + lane);
    (void)off2;

    // 32 blocks per warp, 2-block ILP per iteration.
    #pragma unroll 1
    for (int itp = 0; itp < 16; itp++) {
        #pragma unroll
        for (int half = 0; half < 1; half++) {}  // (structure kept simple)

        float val1[2], val2[2], ssq[2];
        int   obase_ok[2];
        size_t obase[2];

        #pragma unroll
        for (int j = 0; j < 2; j++) {
            const int o  = warp * 32 + itp * 2 + j;   // block id 0..255
            const int ly = o >> 4;
            const int lx = o & 15;
            const int oy = cy0 + ly;
            const int ox = cx0 + lx;
            obase_ok[j] = (oy < OUTD) && (ox < OUTD);
            obase[j] = ((size_t)oy * OUTD + ox) * 36;

            const float* hb = &hist[(ly * HW + lx) * 9];
            val1[j] = hb[off1];
            val2[j] = (lane < 4) ? hb[off2b] : 0.0f;
            ssq[j]  = val1[j] * val1[j] + val2[j] * val2[j];
        }

        // Butterfly reduce both blocks' ssq (independent chains -> ILP).
        #pragma unroll
        for (int m = 16; m >= 1; m >>= 1) {
            ssq[0] += __shfl_xor_sync(0xFFFFFFFFu, ssq[0], m);
            ssq[1] += __shfl_xor_sync(0xFFFFFFFFu, ssq[1], m);
        }

        #pragma unroll
        for (int j = 0; j < 2; j++) {
            if (obase_ok[j]) {
                const float inv = 1.0f / (sqrtf(ssq[j]) + 1e-9f);
                out[obase[j] + lane] = val1[j] * inv;
                if (lane < 4)
                    out[obase[j] + 32 + lane] = val2[j] * inv;
            }
        }
    }
}

extern "C" void kernel_launch(void* const* d_in, const int* in_sizes, int n_in,
                              void* d_out, int out_size)
{
    const float* x = (const float*)d_in[0];
    float* out = (float*)d_out;
    dim3 grid(CELLS / TC, CELLS / TC);   // 32 x 32 tiles = 1024 CTAs
    hog_fused_kernel<<<grid, NT>>>(x, out);
}

// round 13
// speedup vs baseline: 1.1435x; 1.1435x over previous
#include <cuda_runtime.h>

// HoG layer, fused. Phase 1 = R3 scattered gather (2 cells/thread, 24 LDGs
// in flight) + per-cell ssq precompute. Phase 2 = warp-per-block with
// contiguous stores (2-3 store wavefronts/block) and NO shfl reduction:
// block ssq = 4 broadcast LDS of per-cell ssq.
//   input  x: (1, 3, 4096, 4096) f32 ; output feat: (511, 511, 36) f32

#define IMG   4096
#define CELLS 512
#define OUTD  511
#define TC    16          // cells per tile side
#define HW    (TC + 1)    // 17: tile + halo
#define NCELL (HW * HW)   // 289
#define NT    256

__global__ __launch_bounds__(NT)
void hog_fused_kernel(const float* __restrict__ x, float* __restrict__ out)
{
    __shared__ __align__(16) float hist[NCELL * 9];   // 10404 B
    __shared__ float cssq[NCELL];                     // 1156 B

    const int cx0 = blockIdx.x * TC;
    const int cy0 = blockIdx.y * TC;
    const int tid = threadIdx.x;
    const long chs = (long)IMG * IMG;

    // ---- Phase 1: two cells per thread, all 24 loads issued up front ----
    // (No zero pass: every cell a live block reads is a valid cell, and all
    //  9 bins + cssq are written below via selects.)
    float v[2][12];
    bool  valid[2];
    const float* base[2];
    bool  hd[2], hr[2];

    #pragma unroll
    for (int it = 0; it < 2; it++) {
        const int c = tid + it * NT;
        const int lcy = c / HW;
        const int lcx = c - lcy * HW;
        const int cy = cy0 + lcy;
        const int cx = cx0 + lcx;
        valid[it] = (c < NCELL) && (cy < CELLS) && (cx < CELLS);
        const int py = cy * 8 + 7;
        const int px = cx * 8 + 7;
        base[it] = x + (long)py * IMG + px;
        hd[it] = (py + 1 < IMG);
        hr[it] = (px + 1 < IMG);
    }

    #pragma unroll
    for (int it = 0; it < 2; it++) {
        const float* p = base[it];
        const bool va = valid[it];
        const bool vd = va && hd[it];
        const bool vr = va && hr[it];
        #pragma unroll
        for (int ch = 0; ch < 3; ch++) {
            const float* pc = p + ch * chs;
            v[it][ch * 4 + 0] = va ? pc[-IMG] : 0.0f;
            v[it][ch * 4 + 1] = va ? pc[-1]   : 0.0f;
            v[it][ch * 4 + 2] = vd ? pc[IMG]  : 0.0f;
            v[it][ch * 4 + 3] = vr ? pc[1]    : 0.0f;
        }
    }

    #pragma unroll
    for (int it = 0; it < 2; it++) {
        if (!valid[it]) continue;
        const float su = v[it][0] + v[it][4] + v[it][8];
        const float sl = v[it][1] + v[it][5] + v[it][9];
        const float sd = v[it][2] + v[it][6] + v[it][10];
        const float sr = v[it][3] + v[it][7] + v[it][11];

        const float gv = sd - su;
        const float gh = sr - sl;
        const float mag = sqrtf(gv * gv + gh * gh + 1e-6f);
        const float ang = fabsf(atanf(gh / (gv + 1e-9f)))
                          * (180.0f / 3.14159265358979323846f);

        const float t  = ang * 0.05f;                 // ang / 20
        const int   ji = (int)floorf(t - 0.5f);       // in [-1, 4]
        const float vj  = mag * ((float)ji + 1.5f - t);
        const float vj1 = mag - vj;

        const int i0 = (ji < 0) ? 8 : ji;   // mod(ji, 9)
        const int i1 = ji + 1;              // never == i0
        const int c  = tid + it * NT;
        float* hrow = &hist[c * 9];
        #pragma unroll
        for (int b = 0; b < 9; b++)
            hrow[b] = (b == i0) ? vj : ((b == i1) ? vj1 : 0.0f);
        cssq[c] = vj * vj + vj1 * vj1;
    }
    __syncthreads();

    // ---- Phase 2: warp-per-block, contiguous stores, no reduction ----
    const int warp = tid >> 5;
    const int lane = tid & 31;

    // lane -> hist offset for component `lane` (0..31) and `32+lane` (lanes 0..3)
    // comp i: segment s = i/9 (h00,h01,h10,h11), bin b = i%9
    const int s1 = lane / 9;
    const int b1 = lane - s1 * 9;
    const int off1 = ((s1 & 1) ? 9 : 0) + ((s1 & 2) ? HW * 9 : 0) + b1;
    const int off2 = HW * 9 + 9 + 5 + lane;           // comps 32..35: seg 3, bins 5..8

    // 32 blocks per warp, 2-way ILP.
    #pragma unroll 1
    for (int itp = 0; itp < 32; itp += 2) {
        float val1[2], val2[2], inv[2];
        bool  ok[2];
        size_t obase[2];

        #pragma unroll
        for (int j = 0; j < 2; j++) {
            const int o  = warp * 32 + itp + j;       // block id 0..255
            const int ly = o >> 4;
            const int lx = o & 15;
            ok[j] = (cy0 + ly < OUTD) && (cx0 + lx < OUTD);
            obase[j] = ((size_t)(cy0 + ly) * OUTD + (cx0 + lx)) * 36;

            const int cbase = ly * HW + lx;
            const float* hb = &hist[cbase * 9];
            val1[j] = hb[off1];
            val2[j] = (lane < 4) ? hb[off2] : 0.0f;

            // broadcast LDS: all lanes same addresses
            const float ss = cssq[cbase] + cssq[cbase + 1]
                           + cssq[cbase + HW] + cssq[cbase + HW + 1];
            inv[j] = 1.0f / (sqrtf(ss) + 1e-9f);
        }

        #pragma unroll
        for (int j = 0; j < 2; j++) {
            if (ok[j]) {
                out[obase[j] + lane] = val1[j] * inv[j];
                if (lane < 4)
                    out[obase[j] + 32 + lane] = val2[j] * inv[j];
            }
        }
    }
}

extern "C" void kernel_launch(void* const* d_in, const int* in_sizes, int n_in,
                              void* d_out, int out_size)
{
    const float* x = (const float*)d_in[0];
    float* out = (float*)d_out;
    dim3 grid(CELLS / TC, CELLS / TC);   // 32 x 32 tiles = 1024 CTAs
    hog_fused_kernel<<<grid, NT>>>(x, out);
}

// round 14
// speedup vs baseline: 1.5867x; 1.3876x over previous
#include <cuda_runtime.h>

// HoG layer, fused.
// Phase 1:   R3 scattered gather (2 cells/thread, 24 LDGs in flight),
//            all-9-bin hist writes + per-cell ssq (no zero pass).
// Phase 1.5: one thread per block computes inv = 1/(sqrt(ssq)+eps) ONCE.
// Phase 2:   warp-per-block contiguous stores; just LDS + FMUL + STG.
//   input  x: (1, 3, 4096, 4096) f32 ; output feat: (511, 511, 36) f32

#define IMG   4096
#define CELLS 512
#define OUTD  511
#define TC    16          // cells per tile side
#define HW    (TC + 1)    // 17: tile + halo
#define NCELL (HW * HW)   // 289
#define NT    256

__global__ __launch_bounds__(NT)
void hog_fused_kernel(const float* __restrict__ x, float* __restrict__ out)
{
    __shared__ __align__(16) float hist[NCELL * 9];   // 10404 B
    __shared__ float cssq[NCELL];                     // 1156 B
    __shared__ float binv[NT];                        // 1024 B

    const int cx0 = blockIdx.x * TC;
    const int cy0 = blockIdx.y * TC;
    const int tid = threadIdx.x;
    const long chs = (long)IMG * IMG;

    // ---- Phase 1: two cells per thread, all 24 loads issued up front ----
    float v[2][12];
    bool  valid[2];
    const float* base[2];
    bool  hd[2], hr[2];

    #pragma unroll
    for (int it = 0; it < 2; it++) {
        const int c = tid + it * NT;
        const int lcy = c / HW;
        const int lcx = c - lcy * HW;
        const int cy = cy0 + lcy;
        const int cx = cx0 + lcx;
        valid[it] = (c < NCELL) && (cy < CELLS) && (cx < CELLS);
        const int py = cy * 8 + 7;
        const int px = cx * 8 + 7;
        base[it] = x + (long)py * IMG + px;
        hd[it] = (py + 1 < IMG);
        hr[it] = (px + 1 < IMG);
    }

    #pragma unroll
    for (int it = 0; it < 2; it++) {
        const float* p = base[it];
        const bool va = valid[it];
        const bool vd = va && hd[it];
        const bool vr = va && hr[it];
        #pragma unroll
        for (int ch = 0; ch < 3; ch++) {
            const float* pc = p + ch * chs;
            v[it][ch * 4 + 0] = va ? pc[-IMG] : 0.0f;
            v[it][ch * 4 + 1] = va ? pc[-1]   : 0.0f;
            v[it][ch * 4 + 2] = vd ? pc[IMG]  : 0.0f;
            v[it][ch * 4 + 3] = vr ? pc[1]    : 0.0f;
        }
    }

    #pragma unroll
    for (int it = 0; it < 2; it++) {
        if (!valid[it]) continue;
        const float su = v[it][0] + v[it][4] + v[it][8];
        const float sl = v[it][1] + v[it][5] + v[it][9];
        const float sd = v[it][2] + v[it][6] + v[it][10];
        const float sr = v[it][3] + v[it][7] + v[it][11];

        const float gv = sd - su;
        const float gh = sr - sl;
        const float mag = sqrtf(gv * gv + gh * gh + 1e-6f);
        const float ang = fabsf(atanf(gh / (gv + 1e-9f)))
                          * (180.0f / 3.14159265358979323846f);

        const float t  = ang * 0.05f;                 // ang / 20
        const int   ji = (int)floorf(t - 0.5f);       // in [-1, 4]
        const float vj  = mag * ((float)ji + 1.5f - t);
        const float vj1 = mag - vj;

        const int i0 = (ji < 0) ? 8 : ji;   // mod(ji, 9)
        const int i1 = ji + 1;              // never == i0
        const int c  = tid + it * NT;
        float* hrow = &hist[c * 9];
        #pragma unroll
        for (int b = 0; b < 9; b++)
            hrow[b] = (b == i0) ? vj : ((b == i1) ? vj1 : 0.0f);
        cssq[c] = vj * vj + vj1 * vj1;
    }
    __syncthreads();

    // ---- Phase 1.5: one block-inv per thread (256 div/sqrt total) ----
    {
        const int ly = tid >> 4;
        const int lx = tid & 15;
        const int cbase = ly * HW + lx;
        const float ss = cssq[cbase] + cssq[cbase + 1]
                       + cssq[cbase + HW] + cssq[cbase + HW + 1];
        binv[tid] = 1.0f / (sqrtf(ss) + 1e-9f);
    }
    __syncthreads();

    // ---- Phase 2: warp per 2 output rows, contiguous stores ----
    const int warp = tid >> 5;
    const int lane = tid & 31;

    // lane -> hist offsets: comp `lane` (0..31) and comp `32+lane` (lanes 0..3)
    const int s1 = lane / 9;
    const int b1 = lane - s1 * 9;
    const int off1 = ((s1 & 1) ? 9 : 0) + ((s1 & 2) ? HW * 9 : 0) + b1;
    const int off2 = HW * 9 + 9 + 5 + lane;   // comps 32..35: seg h11, bins 5..8

    const int nlx = (cx0 + TC <= OUTD) ? TC : (OUTD - cx0);   // 16 or 15

    #pragma unroll
    for (int ry = 0; ry < 2; ry++) {
        const int ly = 2 * warp + ry;
        const int oy = cy0 + ly;
        if (oy >= OUTD) continue;
        float* orow = out + ((size_t)oy * OUTD + cx0) * 36;
        const int hbase = ly * HW;
        const int bbase = ly * 16;

        // 16 blocks per row, 2-way ILP on the LDS chains.
        #pragma unroll 2
        for (int lx = 0; lx < nlx; lx++) {
            const float inv = binv[bbase + lx];               // broadcast LDS
            const float* hb = &hist[(hbase + lx) * 9];
            const float w1 = hb[off1] * inv;
            float* ob = orow + lx * 36;
            ob[lane] = w1;
            if (lane < 4)
                ob[32 + lane] = hb[off2] * inv;
        }
    }
}

extern "C" void kernel_launch(void* const* d_in, const int* in_sizes, int n_in,
                              void* d_out, int out_size)
{
    const float* x = (const float*)d_in[0];
    float* out = (float*)d_out;
    dim3 grid(CELLS / TC, CELLS / TC);   // 32 x 32 tiles = 1024 CTAs
    hog_fused_kernel<<<grid, NT>>>(x, out);
}